// round 1
// baseline (speedup 1.0000x reference)
#include <cuda_runtime.h>
#include <cstdint>

// BoothGroupQuant:
//   q = clip(round(x*128), -32768, 32767)
//   NAF digits of q: P = ((3q & ~q) >> 1), M = ((q & ~3q) >> 1)   (bit e -> digit +/-1 * 2^e)
//   per group of 16 elems: keep 8 digits with largest exponent
//   (ties at threshold exponent t broken by ascending element index),
//   reconstruct per-element value = (P&keep) - (M&keep), out = val * 2^-7.
//
// Layout: 1 lane = 4 consecutive elements (float4). 1 quad (4 lanes) = 1 group of 16.
// Fully coalesced float4 loads/stores. Quad reductions via shfl.xor(1,2); level-t
// ranking via ballots (whole warp always executes collectives; tail uses `valid`).

#define FULLMASK 0xFFFFFFFFu

__global__ void __launch_bounds__(256)
booth_group_quant_kernel(const float* __restrict__ x,
                         float* __restrict__ out,
                         int n4 /* number of float4 quads */) {
    int i = blockIdx.x * blockDim.x + threadIdx.x;
    bool valid = (i < n4);

    float4 f = make_float4(0.f, 0.f, 0.f, 0.f);
    if (valid) f = reinterpret_cast<const float4*>(x)[i];

    const unsigned lane = threadIdx.x & 31u;

    // ---- quantize + NAF masks for 4 elements ----
    unsigned P[4], M[4], nz[4];
    {
        float fv[4] = {f.x, f.y, f.z, f.w};
        int lt = 0;
#pragma unroll
        for (int j = 0; j < 4; ++j) {
            int q = __float2int_rn(fv[j] * 128.0f);
            q = max(-32768, min(32767, q));
            unsigned un = (unsigned)q;
            unsigned um = un * 3u;
            P[j] = ((um & ~un) >> 1) & 0x1FFFFu;
            M[j] = ((un & ~um) >> 1) & 0x1FFFFu;
            nz[j] = P[j] | M[j];
            lt += __popc(nz[j]);
        }
        // group total nonzero digit count (quad reduce)
        int tot = lt;
        tot += __shfl_xor_sync(FULLMASK, tot, 1);
        tot += __shfl_xor_sync(FULLMASK, tot, 2);

        // ---- binary search: largest t in [0,16] with C(t) >= 8 ----
        // C(e) = sum over group of popc(nz >> e); nonincreasing in e.
        int lo = 0, hi = 17, chi = 0;  // chi tracks C(hi); C(17) = 0
#pragma unroll
        for (int it = 0; it < 5; ++it) {
            int mid = (lo + hi) >> 1;
            int c = __popc(nz[0] >> mid) + __popc(nz[1] >> mid) +
                    __popc(nz[2] >> mid) + __popc(nz[3] >> mid);
            c += __shfl_xor_sync(FULLMASK, c, 1);
            c += __shfl_xor_sync(FULLMASK, c, 2);
            if (c >= 8) { lo = mid; } else { hi = mid; chi = c; }
        }
        const int t = lo;
        const int r = 8 - chi;                       // slots left at level t
        const unsigned hm = (0x1FFFFu << (t + 1)) & 0x1FFFFu;  // bits > t

        // ---- rank elements holding a digit at level t (ascending element order) ----
        unsigned b0 = (nz[0] >> t) & 1u;
        unsigned b1 = (nz[1] >> t) & 1u;
        unsigned b2 = (nz[2] >> t) & 1u;
        unsigned b3 = (nz[3] >> t) & 1u;
        unsigned bal0 = __ballot_sync(FULLMASK, b0 != 0u);
        unsigned bal1 = __ballot_sync(FULLMASK, b1 != 0u);
        unsigned bal2 = __ballot_sync(FULLMASK, b2 != 0u);
        unsigned bal3 = __ballot_sync(FULLMASK, b3 != 0u);
        // lanes strictly below me within my quad
        unsigned qlow = ((1u << lane) - 1u) & (0xFu << (lane & 28u));
        int base = __popc(bal0 & qlow) + __popc(bal1 & qlow) +
                   __popc(bal2 & qlow) + __popc(bal3 & qlow);
        int rk0 = base;
        int rk1 = base + (int)b0;
        int rk2 = rk1 + (int)b1;
        int rk3 = rk2 + (int)b2;

        const unsigned tb = 1u << t;
        unsigned k0 = (nz[0] & hm) | ((b0 && rk0 < r) ? tb : 0u);
        unsigned k1 = (nz[1] & hm) | ((b1 && rk1 < r) ? tb : 0u);
        unsigned k2 = (nz[2] & hm) | ((b2 && rk2 < r) ? tb : 0u);
        unsigned k3 = (nz[3] & hm) | ((b3 && rk3 < r) ? tb : 0u);

        if (tot <= 8) {  // fewer terms than budget: keep everything
            k0 = nz[0]; k1 = nz[1]; k2 = nz[2]; k3 = nz[3];
        }

        // ---- reconstruct: kept value = (P&keep) - (M&keep); out = val * 2^-7 ----
        int v0 = (int)(P[0] & k0) - (int)(M[0] & k0);
        int v1 = (int)(P[1] & k1) - (int)(M[1] & k1);
        int v2 = (int)(P[2] & k2) - (int)(M[2] & k2);
        int v3 = (int)(P[3] & k3) - (int)(M[3] & k3);

        float4 o;
        o.x = (float)v0 * 0.0078125f;
        o.y = (float)v1 * 0.0078125f;
        o.z = (float)v2 * 0.0078125f;
        o.w = (float)v3 * 0.0078125f;
        if (valid) reinterpret_cast<float4*>(out)[i] = o;
    }
}

extern "C" void kernel_launch(void* const* d_in, const int* in_sizes, int n_in,
                              void* d_out, int out_size) {
    const float* x = (const float*)d_in[0];
    float* out = (float*)d_out;
    int n = in_sizes[0];          // total elements (multiple of 16)
    int n4 = n >> 2;              // float4 quads
    int block = 256;
    int grid = (n4 + block - 1) / block;
    booth_group_quant_kernel<<<grid, block>>>(x, out, n4);
}

// round 2
// speedup vs baseline: 1.0642x; 1.0642x over previous
#include <cuda_runtime.h>
#include <cstdint>

// BoothGroupQuant, round 2: 2 groups per thread, packed quad reductions.
//
//   q  = clip(round(x*128), -32768, 32767)          (SF = 2^-7 exact)
//   NAF nonzero-digit mask:  nz = ((3q ^ q) >> 1) & 0x1FFFF
//   P (|+1| digits) = nz & (3q >> 1),  M (-1 digits) = nz & (q >> 1)
//   per 16-elem group keep the 8 digits with largest exponent
//   (ties at threshold exponent t -> ascending element index),
//   value = (P&keep) - (M&keep),  out = value * 2^-7.
//
// Layout: lane = 1 float4 per group; quad of lanes = 1 group of 16.
// Each thread processes TWO groups (A at gid, B at gid+h) so the two binary
// searches interleave (ILP hides SHFL latency) and each pair of quad-reduce
// SHFLs serves both groups via 16-bit packing. Ranking uses a width-4
// shfl_up scan on byte-packed counts. No divergence around collectives.

#define FULLMASK 0xFFFFFFFFu

__device__ __forceinline__ void quant4(float4 f, unsigned un[4], unsigned nz[4]) {
    float fv[4] = {f.x, f.y, f.z, f.w};
#pragma unroll
    for (int j = 0; j < 4; ++j) {
        int q = __float2int_rn(fv[j] * 128.0f);
        q = max(-32768, min(32767, q));
        unsigned u = (unsigned)q;
        un[j] = u;
        nz[j] = (((u * 3u) ^ u) >> 1) & 0x1FFFFu;
    }
}

__global__ void __launch_bounds__(256)
booth_group_quant_kernel(const float* __restrict__ x,
                         float* __restrict__ out,
                         int n4, int h /* f4 per half, multiple of 4 */) {
    const int gid = blockIdx.x * blockDim.x + threadIdx.x;
    const int i0 = gid;
    const int i1 = gid + h;
    const bool v0 = (i0 < n4) && (gid < h);
    const bool v1 = (i1 < n4);

    float4 fA = make_float4(0.f, 0.f, 0.f, 0.f);
    float4 fB = make_float4(0.f, 0.f, 0.f, 0.f);
    if (v0) fA = reinterpret_cast<const float4*>(x)[i0];
    if (v1) fB = reinterpret_cast<const float4*>(x)[i1];

    unsigned unA[4], nzA[4], unB[4], nzB[4];
    quant4(fA, unA, nzA);
    quant4(fB, unB, nzB);

    // ---- dual binary search: largest t with C(t) >= 8 (C nonincreasing) ----
    // When even C(0) < 8, converges to t=0, r=8-C(1) which keeps all digits.
    int lo0 = 0, hi0 = 17, chi0 = 0;
    int lo1 = 0, hi1 = 17, chi1 = 0;
#pragma unroll
    for (int it = 0; it < 5; ++it) {
        int m0 = (lo0 + hi0) >> 1;
        int m1 = (lo1 + hi1) >> 1;
        int c0 = __popc(nzA[0] >> m0) + __popc(nzA[1] >> m0) +
                 __popc(nzA[2] >> m0) + __popc(nzA[3] >> m0);
        int c1 = __popc(nzB[0] >> m1) + __popc(nzB[1] >> m1) +
                 __popc(nzB[2] >> m1) + __popc(nzB[3] >> m1);
        int pk = c0 | (c1 << 16);                 // fields <= 144, no carry-out
        pk += __shfl_xor_sync(FULLMASK, pk, 1);
        pk += __shfl_xor_sync(FULLMASK, pk, 2);
        c0 = pk & 0xFFFF;
        c1 = pk >> 16;
        if (c0 >= 8) lo0 = m0; else { hi0 = m0; chi0 = c0; }
        if (c1 >= 8) lo1 = m1; else { hi1 = m1; chi1 = c1; }
    }
    const int t0 = lo0, r0 = 8 - chi0;
    const int t1 = lo1, r1 = 8 - chi1;
    const unsigned hm0 = (0x1FFFFu << (t0 + 1)) & 0x1FFFFu;
    const unsigned hm1 = (0x1FFFFu << (t1 + 1)) & 0x1FFFFu;

    // ---- rank level-t digits in ascending element order (quad prefix scan) ----
    unsigned bA0 = (nzA[0] >> t0) & 1u, bA1 = (nzA[1] >> t0) & 1u;
    unsigned bA2 = (nzA[2] >> t0) & 1u, bA3 = (nzA[3] >> t0) & 1u;
    unsigned bB0 = (nzB[0] >> t1) & 1u, bB1 = (nzB[1] >> t1) & 1u;
    unsigned bB2 = (nzB[2] >> t1) & 1u, bB3 = (nzB[3] >> t1) & 1u;
    int cntA = (int)(bA0 + bA1 + bA2 + bA3);
    int cntB = (int)(bB0 + bB1 + bB2 + bB3);

    int inc = cntA | (cntB << 8);                 // fields <= 4, sums <= 16
    const int qlane = threadIdx.x & 3;
    int u1 = __shfl_up_sync(FULLMASK, inc, 1, 4);
    if (qlane >= 1) inc += u1;
    int u2 = __shfl_up_sync(FULLMASK, inc, 2, 4);
    if (qlane >= 2) inc += u2;
    int baseA = (inc & 0xFF) - cntA;              // exclusive prefix
    int baseB = (inc >> 8)  - cntB;

    // ---- build keep masks ----
    unsigned kA0, kA1, kA2, kA3, kB0, kB1, kB2, kB3;
    {
        int rk = baseA;
        kA0 = (nzA[0] & hm0) | (((rk < r0) ? bA0 : 0u) << t0); rk += (int)bA0;
        kA1 = (nzA[1] & hm0) | (((rk < r0) ? bA1 : 0u) << t0); rk += (int)bA1;
        kA2 = (nzA[2] & hm0) | (((rk < r0) ? bA2 : 0u) << t0); rk += (int)bA2;
        kA3 = (nzA[3] & hm0) | (((rk < r0) ? bA3 : 0u) << t0);
    }
    {
        int rk = baseB;
        kB0 = (nzB[0] & hm1) | (((rk < r1) ? bB0 : 0u) << t1); rk += (int)bB0;
        kB1 = (nzB[1] & hm1) | (((rk < r1) ? bB1 : 0u) << t1); rk += (int)bB1;
        kB2 = (nzB[2] & hm1) | (((rk < r1) ? bB2 : 0u) << t1); rk += (int)bB2;
        kB3 = (nzB[3] & hm1) | (((rk < r1) ? bB3 : 0u) << t1);
    }

    // ---- reconstruct: v = (k & (3u>>1)) - (k & (u>>1)); out = v * 2^-7 ----
#define RECON(k, u) ((int)((k) & (((u) * 3u) >> 1)) - (int)((k) & ((u) >> 1)))
    float4 oA, oB;
    oA.x = (float)RECON(kA0, unA[0]) * 0.0078125f;
    oA.y = (float)RECON(kA1, unA[1]) * 0.0078125f;
    oA.z = (float)RECON(kA2, unA[2]) * 0.0078125f;
    oA.w = (float)RECON(kA3, unA[3]) * 0.0078125f;
    oB.x = (float)RECON(kB0, unB[0]) * 0.0078125f;
    oB.y = (float)RECON(kB1, unB[1]) * 0.0078125f;
    oB.z = (float)RECON(kB2, unB[2]) * 0.0078125f;
    oB.w = (float)RECON(kB3, unB[3]) * 0.0078125f;
#undef RECON

    if (v0) reinterpret_cast<float4*>(out)[i0] = oA;
    if (v1) reinterpret_cast<float4*>(out)[i1] = oB;
}

extern "C" void kernel_launch(void* const* d_in, const int* in_sizes, int n_in,
                              void* d_out, int out_size) {
    const float* x = (const float*)d_in[0];
    float* out = (float*)d_out;
    int n = in_sizes[0];
    int n4 = n >> 2;                       // float4 count
    int h = (((n4 + 1) >> 1) + 3) & ~3;    // f4 per half, quad-aligned
    int block = 256;
    int grid = (h + block - 1) / block;
    booth_group_quant_kernel<<<grid, block>>>(x, out, n4, h);
}

// round 3
// speedup vs baseline: 1.3473x; 1.2661x over previous
#include <cuda_runtime.h>
#include <cstdint>

// BoothGroupQuant, round 3: one thread = one full group of 16. No warp
// collectives at all; per-group scalar work (threshold search, tie ranking)
// executes once per group instead of once per lane.
//
//   q  = clip(round(x*128), -32768, 32767)
//   NAF masks (proved to fit in 16 bits for this range):
//     nz = ((3q ^ q) >> 1) & 0xFFFF      (positions of nonzero digits)
//     M  = ((q & ~3q) >> 1) & 0xFFFF     (positions of -1 digits)
//   keep the 8 largest-exponent digits per group (ties at threshold exponent
//   t resolved in ascending element order); kept value per element:
//     v = (k&P) - (k&M) = k - 2*(k&M)    (k subset of nz, P = nz ^ M)
//   out = v * 2^-7.
//
// Threshold: CSA adder tree turns the 16 masks into 5 popcount bit-planes
// (column counts per exponent), then a 4-probe binary search finds the
// largest t with S(t) = #digits at exponent >= t  >= 8.

#define CSA(s, c, a, b, d)            \
    do {                              \
        unsigned _x = (a) ^ (b);      \
        s = _x ^ (d);                 \
        c = ((a) & (b)) | (_x & (d)); \
    } while (0)

__global__ void __launch_bounds__(128)
booth_group_quant_kernel(const float* __restrict__ x,
                         float* __restrict__ out,
                         int ngroups) {
    const int g = blockIdx.x * blockDim.x + threadIdx.x;
    if (g >= ngroups) return;

    const float4* __restrict__ xv = reinterpret_cast<const float4*>(x) + (size_t)g * 4;
    float4 f0 = xv[0], f1 = xv[1], f2 = xv[2], f3 = xv[3];

    // ---- quantize + pack nz|M<<16 for 16 elements ----
    unsigned pk[16];
    {
        float fv[16] = {f0.x, f0.y, f0.z, f0.w, f1.x, f1.y, f1.z, f1.w,
                        f2.x, f2.y, f2.z, f2.w, f3.x, f3.y, f3.z, f3.w};
#pragma unroll
        for (int j = 0; j < 16; ++j) {
            int q = __float2int_rn(fv[j] * 128.0f);
            q = max(-32768, min(32767, q));
            unsigned u  = (unsigned)q;
            unsigned u3 = u * 3u;
            unsigned nz = ((u3 ^ u) >> 1) & 0xFFFFu;
            unsigned m  = ((u & ~u3) >> 1) & 0xFFFFu;
            pk[j] = nz | (m << 16);
        }
    }

    // ---- CSA tree: per-column counts of nz bits as 5 bit-planes ----
    // (high halves carry M-column garbage; stripped by &0xFFFF before popc)
    unsigned P0, P1, P2, P3, P4;
    {
        unsigned s1, c1, s2, c2, s3, c3, s4, c4, s5, c5, s6, c6, s7, c7;
        CSA(s1, c1, pk[0], pk[1], pk[2]);
        CSA(s2, c2, pk[3], pk[4], pk[5]);
        CSA(s3, c3, pk[6], pk[7], pk[8]);
        CSA(s4, c4, pk[9], pk[10], pk[11]);
        CSA(s5, c5, pk[12], pk[13], pk[14]);
        CSA(s6, c6, s1, s2, s3);
        CSA(s7, c7, s4, s5, pk[15]);
        P0 = s6 ^ s7;
        unsigned h1 = s6 & s7;
        unsigned sA, cA, sB, cB, sC, cC, sD, cD;
        CSA(sA, cA, c1, c2, c3);
        CSA(sB, cB, c4, c5, c6);
        CSA(sC, cC, c7, h1, sA);
        P1 = sB ^ sC;
        unsigned h2 = sB & sC;
        CSA(sD, cD, cA, cB, cC);
        P2 = sD ^ h2;
        unsigned h3 = sD & h2;
        P3 = cD ^ h3;
        P4 = cD & h3;
        P0 &= 0xFFFFu; P1 &= 0xFFFFu; P2 &= 0xFFFFu; P3 &= 0xFFFFu; P4 &= 0xFFFFu;
    }

    // ---- binary search: largest t in [0,15] with S(t) >= 8; S(16)=0 ----
    int lo = 0, hi = 16, chi = 0;
#pragma unroll
    for (int it = 0; it < 4; ++it) {
        int m = (lo + hi) >> 1;
        int s = __popc(P0 >> m) + 2 * __popc(P1 >> m) + 4 * __popc(P2 >> m) +
                8 * __popc(P3 >> m) + 16 * __popc(P4 >> m);
        if (s >= 8) lo = m; else { hi = m; chi = s; }
    }
    const int t = lo;
    int rk = 8 - chi;                                   // slots at level t
    const unsigned hm = (0xFFFFu << (t + 1)) & 0xFFFFu; // exponents > t

    // ---- rank walk + reconstruct + store ----
    float4 o[4];
    float* op = &o[0].x;
#pragma unroll
    for (int j = 0; j < 16; ++j) {
        unsigned w    = pk[j];
        unsigned b    = (w >> t) & 1u;
        unsigned take = (rk > 0) ? b : 0u;
        rk -= (int)take;
        unsigned k  = (w & hm) | (take << t);
        unsigned km = k & (w >> 16);
        int v = (int)k - 2 * (int)km;
        op[j] = (float)v * 0.0078125f;
    }
    float4* __restrict__ ov = reinterpret_cast<float4*>(out) + (size_t)g * 4;
    ov[0] = o[0]; ov[1] = o[1]; ov[2] = o[2]; ov[3] = o[3];
}

extern "C" void kernel_launch(void* const* d_in, const int* in_sizes, int n_in,
                              void* d_out, int out_size) {
    const float* x = (const float*)d_in[0];
    float* out = (float*)d_out;
    int n = in_sizes[0];
    int ngroups = n >> 4;  // 16 elements per group
    int block = 128;
    int grid = (ngroups + block - 1) / block;
    booth_group_quant_kernel<<<grid, block>>>(x, out, ngroups);
}